// round 1
// baseline (speedup 1.0000x reference)
#include <cuda_runtime.h>
#include <math.h>

// Problem dims (fixed by setup_inputs)
#define BB   8
#define C3   3
#define HH   512
#define WW   512
#define HP   128
#define WP   128
#define CF   256
#define SP   (HP*WP)            // 16384 spatial per plane
#define NF   (BB*CF*SP)         // 33554432 F_in elements

// Device scratch (no allocations allowed)
__device__ double g_sum;
__device__ double g_sumsq;
__device__ float  g_stats[2];          // [0] = mean*scale, [1] = scale
__device__ float  g_img_ds[BB*C3*SP];  // 4x4 avg-pooled img  (1.5 MiB)
__device__ float  g_mask01[BB*SP];     // 4x4 max-pooled binary mask
__device__ float  g_dh[BB*SP];         // distance-valued D_h

// ---------------------------------------------------------------- init
__global__ void init_kernel() {
    g_sum = 0.0;
    g_sumsq = 0.0;
}

// ---------------------------------------------------------------- global sum / sumsq of F_in
__global__ void reduce_kernel(const float4* __restrict__ F) {
    __shared__ double s_s[256];
    __shared__ double s_q[256];
    const int tid = threadIdx.x;
    long i = (long)blockIdx.x * blockDim.x + tid;
    const long stride = (long)gridDim.x * blockDim.x;
    float ps = 0.f, pq = 0.f;
    for (; i < NF / 4; i += stride) {
        float4 v = F[i];
        ps += v.x + v.y + v.z + v.w;
        pq += v.x * v.x + v.y * v.y + v.z * v.z + v.w * v.w;
    }
    s_s[tid] = (double)ps;
    s_q[tid] = (double)pq;
    __syncthreads();
    for (int off = 128; off > 0; off >>= 1) {
        if (tid < off) {
            s_s[tid] += s_s[tid + off];
            s_q[tid] += s_q[tid + off];
        }
        __syncthreads();
    }
    if (tid == 0) {
        atomicAdd(&g_sum,   s_s[0]);
        atomicAdd(&g_sumsq, s_q[0]);
    }
}

// ---------------------------------------------------------------- finalize stats
__global__ void finalize_kernel() {
    double n = (double)NF;
    double mean = g_sum / n;
    double var = (g_sumsq - g_sum * g_sum / n) / (n - 1.0);
    double scale = 1.0 / sqrt(var * var + 1e-5);
    g_stats[0] = (float)(mean * scale);
    g_stats[1] = (float)scale;
}

// ---------------------------------------------------------------- 4x4 pools (img avg, mask max)
__global__ void pool_kernel(const float* __restrict__ img,
                            const float* __restrict__ mask) {
    const int total_img = BB * C3 * SP;   // 393216
    const int total     = total_img + BB * SP;
    int idx = blockIdx.x * blockDim.x + threadIdx.x;
    if (idx >= total) return;
    if (idx < total_img) {
        int wp = idx & 127;
        int hp = (idx >> 7) & 127;
        int ch = (idx >> 14) % 3;
        int b  = idx / (C3 * SP);
        const float* p = img + ((size_t)(b * 3 + ch) * HH + hp * 4) * WW + wp * 4;
        float s = 0.f;
        #pragma unroll
        for (int r = 0; r < 4; r++) {
            float4 v = *(const float4*)(p + (size_t)r * WW);
            s += v.x + v.y + v.z + v.w;
        }
        g_img_ds[idx] = s * (1.f / 16.f);
    } else {
        int m  = idx - total_img;
        int wp = m & 127;
        int hp = (m >> 7) & 127;
        int b  = m >> 14;
        const float* p = mask + ((size_t)(b * 3) * HH + hp * 4) * WW + wp * 4;
        float mx = 0.f;
        #pragma unroll
        for (int r = 0; r < 4; r++) {
            float4 v = *(const float4*)(p + (size_t)r * WW);
            mx = fmaxf(mx, fmaxf(fmaxf(v.x, v.y), fmaxf(v.z, v.w)));
        }
        g_mask01[m] = mx;
    }
}

// ---------------------------------------------------------------- Chebyshev distance transform
// 5 iterations of (3x3 dilate -> assign 2^-i to newly reached pixels) is exactly:
//   d = Chebyshev distance to nearest mask==1 pixel; value = (d<=5) ? 2^-d : 0
__global__ void dilate_kernel() {
    __shared__ float tile[26][27];   // 16x16 block + halo 5, padded
    const int tx = threadIdx.x, ty = threadIdx.y;
    const int bx = blockIdx.x * 16, by = blockIdx.y * 16;
    const int b = blockIdx.z;
    const float* mbase = &g_mask01[b * SP];

    for (int yy = ty; yy < 26; yy += 16) {
        int gy = by + yy - 5;
        for (int xx = tx; xx < 26; xx += 16) {
            int gx = bx + xx - 5;
            float v = 0.f;
            if (gy >= 0 && gy < HP && gx >= 0 && gx < WP)
                v = mbase[gy * WP + gx];
            tile[yy][xx] = v;
        }
    }
    __syncthreads();

    int dmin = 6;
    #pragma unroll
    for (int dy = -5; dy <= 5; dy++) {
        #pragma unroll
        for (int dx = -5; dx <= 5; dx++) {
            if (tile[ty + 5 + dy][tx + 5 + dx] > 0.5f) {
                int ady = dy < 0 ? -dy : dy;
                int adx = dx < 0 ? -dx : dx;
                int d = ady > adx ? ady : adx;
                dmin = d < dmin ? d : dmin;
            }
        }
    }
    float val = (dmin <= 5) ? exp2f(-(float)dmin) : 0.f;
    g_dh[b * SP + (by + ty) * WP + (bx + tx)] = val;
}

// ---------------------------------------------------------------- fused epilogue
__global__ void __launch_bounds__(256)
main_kernel(const float4* __restrict__ F,
            const float*  __restrict__ gw, const float* __restrict__ gB,
            const float*  __restrict__ bw, const float* __restrict__ bB,
            float4* __restrict__ out) {
    int idx = blockIdx.x * blockDim.x + threadIdx.x;   // one float4 per thread
    int w  = (idx & 31) << 2;        // WP/4 = 32 vec positions
    int h  = (idx >> 5) & 127;
    int c  = (idx >> 12) & 255;
    int b  = idx >> 20;

    int hw = h * WP + w;
    int sb = b * SP + hw;
    int ib = b * 3 * SP + hw;

    float4 dh = *(const float4*)&g_dh[sb];
    float4 p0 = *(const float4*)&g_img_ds[ib];
    float4 p1 = *(const float4*)&g_img_ds[ib + SP];
    float4 p2 = *(const float4*)&g_img_ds[ib + 2 * SP];

    float gw0 = __ldg(&gw[c * 3]), gw1 = __ldg(&gw[c * 3 + 1]), gw2 = __ldg(&gw[c * 3 + 2]);
    float gbc = __ldg(&gB[c]);
    float bw0 = __ldg(&bw[c * 3]), bw1 = __ldg(&bw[c * 3 + 1]), bw2 = __ldg(&bw[c * 3 + 2]);
    float bbc = __ldg(&bB[c]);

    float ms = g_stats[0];   // mean*scale
    float sc = g_stats[1];   // 1/sqrt(var^2 + 1e-5)

    float4 f = F[idx];
    float4 o;
    {
        float gcoef = fmaf(gw2, p0.x * 0.f + p2.x, fmaf(gw1, p1.x, fmaf(gw0, p0.x, gbc))) * dh.x;
        // (note: the p0.x*0.f term is eliminated; written plainly below for clarity)
        gcoef = fmaf(gw2, p2.x, fmaf(gw1, p1.x, fmaf(gw0, p0.x, gbc))) * dh.x;
        float bcoef = fmaf(bw2, p2.x, fmaf(bw1, p1.x, fmaf(bw0, p0.x, bbc))) * dh.x;
        float fn = fmaf(f.x, sc, -ms);
        o.x = fmaf(fn, gcoef, bcoef);
    }
    {
        float gcoef = fmaf(gw2, p2.y, fmaf(gw1, p1.y, fmaf(gw0, p0.y, gbc))) * dh.y;
        float bcoef = fmaf(bw2, p2.y, fmaf(bw1, p1.y, fmaf(bw0, p0.y, bbc))) * dh.y;
        float fn = fmaf(f.y, sc, -ms);
        o.y = fmaf(fn, gcoef, bcoef);
    }
    {
        float gcoef = fmaf(gw2, p2.z, fmaf(gw1, p1.z, fmaf(gw0, p0.z, gbc))) * dh.z;
        float bcoef = fmaf(bw2, p2.z, fmaf(bw1, p1.z, fmaf(bw0, p0.z, bbc))) * dh.z;
        float fn = fmaf(f.z, sc, -ms);
        o.z = fmaf(fn, gcoef, bcoef);
    }
    {
        float gcoef = fmaf(gw2, p2.w, fmaf(gw1, p1.w, fmaf(gw0, p0.w, gbc))) * dh.w;
        float bcoef = fmaf(bw2, p2.w, fmaf(bw1, p1.w, fmaf(bw0, p0.w, bbc))) * dh.w;
        float fn = fmaf(f.w, sc, -ms);
        o.w = fmaf(fn, gcoef, bcoef);
    }
    out[idx] = o;
}

// ---------------------------------------------------------------- launch
extern "C" void kernel_launch(void* const* d_in, const int* in_sizes, int n_in,
                              void* d_out, int out_size) {
    const float* F_in    = (const float*)d_in[0];
    const float* img_p   = (const float*)d_in[1];
    const float* mask    = (const float*)d_in[2];
    const float* gamma_w = (const float*)d_in[3];
    const float* gamma_b = (const float*)d_in[4];
    const float* beta_w  = (const float*)d_in[5];
    const float* beta_b  = (const float*)d_in[6];
    // d_in[7] = n_ds (==2), d_in[8] = n (==2): fixed by problem shapes; hardcoded.
    float* out = (float*)d_out;

    init_kernel<<<1, 1>>>();
    reduce_kernel<<<2048, 256>>>((const float4*)F_in);

    {
        int total = BB * C3 * SP + BB * SP;
        pool_kernel<<<(total + 255) / 256, 256>>>(img_p, mask);
    }

    {
        dim3 grid(WP / 16, HP / 16, BB);
        dim3 blk(16, 16);
        dilate_kernel<<<grid, blk>>>();
    }

    finalize_kernel<<<1, 1>>>();

    main_kernel<<<NF / 4 / 256, 256>>>((const float4*)F_in,
                                       gamma_w, gamma_b, beta_w, beta_b,
                                       (float4*)out);
}